// round 1
// baseline (speedup 1.0000x reference)
#include <cuda_runtime.h>
#include <cstdint>

#define B_   1024
#define T_   64
#define D_   512
#define H_   512
#define G4_  2048   // 4*H

// ---------------- scratch (device globals; no allocation allowed) ----------
__device__ float g_xp[(size_t)T_ * B_ * G4_];   // 512 MB: precomputed x@W + bias, [T][B][4H]
__device__ float g_z[(size_t)B_ * G4_];         // 8 MB: per-step pre-activation
__device__ float g_h[(size_t)B_ * H_];          // 2 MB
__device__ float g_c[(size_t)B_ * H_];          // 2 MB

// ---------------- helpers ---------------------------------------------------
__device__ __forceinline__ uint32_t f2tf32(float f) {
    uint32_t r;
    asm("cvt.rna.tf32.f32 %0, %1;" : "=r"(r) : "f"(f));
    return r;
}

__device__ __forceinline__ void mma8(float* c, const uint32_t* a, const uint32_t* b) {
    asm volatile(
        "mma.sync.aligned.m16n8k8.row.col.f32.tf32.tf32.f32 "
        "{%0,%1,%2,%3}, {%4,%5,%6,%7}, {%8,%9}, {%0,%1,%2,%3};\n"
        : "+f"(c[0]), "+f"(c[1]), "+f"(c[2]), "+f"(c[3])
        : "r"(a[0]), "r"(a[1]), "r"(a[2]), "r"(a[3]),
          "r"(b[0]), "r"(b[1]));
}

__device__ __forceinline__ float sigm(float x) { return 1.0f / (1.0f + expf(-x)); }

// ---------------- GEMM ------------------------------------------------------
// MODE 0: XP[r] = X_perm[r] @ W + bias      (r = t*B + b, A-row fetched as X[b][t][:])
//         grid = (G4_/128, T_*B_/128)
// MODE 1: Z = g_h @ U + XP[t]               grid = (G4_/128, B_/128)
template<int MODE>
__global__ void __launch_bounds__(256, 1)
gemm_tf32(const float* __restrict__ Aext, const float* __restrict__ Bm,
          const float* __restrict__ bias, int t)
{
    constexpr int BMt = 128, BNt = 128, BKt = 16;
    constexpr int N = G4_, K = D_;

    __shared__ __align__(16) uint32_t As[BKt][BMt + 4];
    __shared__ __align__(16) uint32_t Bs[BKt][BNt + 4];

    const int tid = threadIdx.x;
    const int m0 = blockIdx.y * BMt;
    const int n0 = blockIdx.x * BNt;

    const float* A;
    const float* Cadd;
    float* Cout;
    if (MODE == 0) { A = Aext; Cadd = bias; Cout = g_xp; }
    else           { A = g_h;  Cadd = g_xp + (size_t)t * ((size_t)B_ * G4_); Cout = g_z; }

    // ---- global-load thread mapping
    const int ar = tid >> 2;            // 0..63 (row within half-tile)
    const int ac = (tid & 3) * 4;       // 0,4,8,12 (k offset)
    const float* aPtr[2];
#pragma unroll
    for (int it = 0; it < 2; it++) {
        int rg = m0 + it * 64 + ar;
        size_t arow;
        if (MODE == 0) {
            int tt = rg >> 10;          // B_ = 1024
            int bb = rg & 1023;
            arow = (size_t)bb * T_ + tt;
        } else {
            arow = (size_t)rg;
        }
        aPtr[it] = A + arow * K + ac;
    }
    const int br = tid >> 5;            // 0..7
    const int bc = (tid & 31) * 4;      // 0..124
    const float* bPtr[2];
#pragma unroll
    for (int it = 0; it < 2; it++)
        bPtr[it] = Bm + (size_t)(br + it * 8) * N + n0 + bc;

    // ---- compute thread mapping
    const int warp = tid >> 5, lane = tid & 31;
    const int wm = warp >> 2;           // 0..1 : 64 rows
    const int wn = warp & 3;            // 0..3 : 32 cols
    const int gq = lane >> 2;           // 0..7
    const int tq = lane & 3;            // 0..3

    float acc[4][4][4];
#pragma unroll
    for (int i = 0; i < 4; i++)
#pragma unroll
        for (int j = 0; j < 4; j++)
#pragma unroll
            for (int k = 0; k < 4; k++) acc[i][j][k] = 0.0f;

    // ---- prefetch first tile to registers
    float4 pa[2], pb[2];
#pragma unroll
    for (int it = 0; it < 2; it++) {
        pa[it] = *(const float4*)(aPtr[it]);
        pb[it] = *(const float4*)(bPtr[it]);
    }

    for (int kt = 0; kt < K / BKt; kt++) {
        __syncthreads();
        // store registers -> smem (convert to tf32 once here)
#pragma unroll
        for (int it = 0; it < 2; it++) {
            As[ac + 0][it * 64 + ar] = f2tf32(pa[it].x);
            As[ac + 1][it * 64 + ar] = f2tf32(pa[it].y);
            As[ac + 2][it * 64 + ar] = f2tf32(pa[it].z);
            As[ac + 3][it * 64 + ar] = f2tf32(pa[it].w);
            uint4 bv = make_uint4(f2tf32(pb[it].x), f2tf32(pb[it].y),
                                  f2tf32(pb[it].z), f2tf32(pb[it].w));
            *(uint4*)&Bs[it * 8 + br][bc] = bv;
        }
        __syncthreads();

        // prefetch next tile while computing on this one
        if (kt + 1 < K / BKt) {
            const int k0 = (kt + 1) * BKt;
#pragma unroll
            for (int it = 0; it < 2; it++) {
                pa[it] = *(const float4*)(aPtr[it] + k0);
                pb[it] = *(const float4*)(bPtr[it] + (size_t)k0 * N);
            }
        }

#pragma unroll
        for (int k8 = 0; k8 < BKt; k8 += 8) {
            uint32_t afr[4][4], bfr[4][2];
#pragma unroll
            for (int mf = 0; mf < 4; mf++) {
                const int r0 = wm * 64 + mf * 16 + gq;
                afr[mf][0] = As[k8 + tq][r0];
                afr[mf][1] = As[k8 + tq][r0 + 8];
                afr[mf][2] = As[k8 + tq + 4][r0];
                afr[mf][3] = As[k8 + tq + 4][r0 + 8];
            }
#pragma unroll
            for (int nf = 0; nf < 4; nf++) {
                const int c0 = wn * 32 + nf * 8 + gq;
                bfr[nf][0] = Bs[k8 + tq][c0];
                bfr[nf][1] = Bs[k8 + tq + 4][c0];
            }
#pragma unroll
            for (int mf = 0; mf < 4; mf++)
#pragma unroll
                for (int nf = 0; nf < 4; nf++)
                    mma8(acc[mf][nf], afr[mf], bfr[nf]);
        }
    }

    // ---- epilogue
#pragma unroll
    for (int mf = 0; mf < 4; mf++) {
#pragma unroll
        for (int nf = 0; nf < 4; nf++) {
            const int row = m0 + wm * 64 + mf * 16 + gq;
            const int col = n0 + wn * 32 + nf * 8 + tq * 2;
            float2 v0 = make_float2(acc[mf][nf][0], acc[mf][nf][1]);
            float2 v1 = make_float2(acc[mf][nf][2], acc[mf][nf][3]);
            if (MODE == 0) {
                const float b0 = Cadd[col], b1 = Cadd[col + 1];
                v0.x += b0; v0.y += b1; v1.x += b0; v1.y += b1;
            } else {
                float2 a0 = *(const float2*)&Cadd[(size_t)row * N + col];
                float2 a1 = *(const float2*)&Cadd[(size_t)(row + 8) * N + col];
                v0.x += a0.x; v0.y += a0.y; v1.x += a1.x; v1.y += a1.y;
            }
            *(float2*)&Cout[(size_t)row * N + col] = v0;
            *(float2*)&Cout[(size_t)(row + 8) * N + col] = v1;
        }
    }
}

// ---------------- elementwise LSTM cell -------------------------------------
__global__ void __launch_bounds__(256)
lstm_gates(float* __restrict__ out, int t)
{
    const int gid = blockIdx.x * blockDim.x + threadIdx.x;  // B_*H_/4 = 131072
    const int b = gid >> 7;              // / (H_/4)
    const int j = (gid & 127) * 4;

    const float* zr = g_z + (size_t)b * G4_;
    const float4 zi = *(const float4*)(zr + j);
    const float4 zf = *(const float4*)(zr + H_ + j);
    const float4 zg = *(const float4*)(zr + 2 * H_ + j);
    const float4 zo = *(const float4*)(zr + 3 * H_ + j);

    float4 cc = *(const float4*)(g_c + (size_t)b * H_ + j);
    float4 hh;

    {
        const float i_ = sigm(zi.x), f_ = sigm(zf.x), g_ = tanhf(zg.x), o_ = sigm(zo.x);
        cc.x = f_ * cc.x + i_ * g_;  hh.x = o_ * tanhf(cc.x);
    }
    {
        const float i_ = sigm(zi.y), f_ = sigm(zf.y), g_ = tanhf(zg.y), o_ = sigm(zo.y);
        cc.y = f_ * cc.y + i_ * g_;  hh.y = o_ * tanhf(cc.y);
    }
    {
        const float i_ = sigm(zi.z), f_ = sigm(zf.z), g_ = tanhf(zg.z), o_ = sigm(zo.z);
        cc.z = f_ * cc.z + i_ * g_;  hh.z = o_ * tanhf(cc.z);
    }
    {
        const float i_ = sigm(zi.w), f_ = sigm(zf.w), g_ = tanhf(zg.w), o_ = sigm(zo.w);
        cc.w = f_ * cc.w + i_ * g_;  hh.w = o_ * tanhf(cc.w);
    }

    *(float4*)(g_c + (size_t)b * H_ + j) = cc;
    *(float4*)(g_h + (size_t)b * H_ + j) = hh;
    *(float4*)(out + (size_t)b * ((size_t)T_ * H_) + (size_t)t * H_ + j) = hh;
}

__global__ void zero_hc()
{
    const int i = blockIdx.x * blockDim.x + threadIdx.x;
    if (i < B_ * H_) { g_h[i] = 0.0f; g_c[i] = 0.0f; }
}

// ---------------- launch -----------------------------------------------------
extern "C" void kernel_launch(void* const* d_in, const int* in_sizes, int n_in,
                              void* d_out, int out_size)
{
    const float* X    = (const float*)d_in[0];   // [B, T, D]
    const float* W    = (const float*)d_in[1];   // [D, 4H]
    const float* U    = (const float*)d_in[2];   // [H, 4H]
    const float* bias = (const float*)d_in[3];   // [4H]
    float* out = (float*)d_out;                  // [B, T, H]

    zero_hc<<<(B_ * H_ + 255) / 256, 256>>>();

    // Stage 1: XP[t][b] = X[b][t] @ W + bias  (one big parallel GEMM)
    dim3 g1(G4_ / 128, (T_ * B_) / 128);         // 16 x 512
    gemm_tf32<0><<<g1, 256>>>(X, W, bias, 0);

    // Stage 2: 64 sequential recurrent steps
    dim3 g2(G4_ / 128, B_ / 128);                // 16 x 8
    for (int t = 0; t < T_; t++) {
        gemm_tf32<1><<<g2, 256>>>(nullptr, U, nullptr, t);
        lstm_gates<<<(B_ * H_ / 4) / 256, 256>>>(out, t);
    }
}

// round 2
// speedup vs baseline: 1.1272x; 1.1272x over previous
#include <cuda_runtime.h>
#include <cstdint>

#define B_   1024
#define T_   64
#define D_   512
#define H_   512
#define G4_  2048   // 4*H

// ---------------- device scratch (no allocation allowed) --------------------
__device__ float g_xp[(size_t)T_ * B_ * G4_];   // 512 MB: x@W + bias, [T][B][4H]
__device__ float g_xt[(size_t)T_ * D_ * B_];    // 128 MB: tf32-rounded X, [T][D][B]
__device__ float g_w32[(size_t)D_ * G4_];       // 4 MB: tf32-rounded kernel
__device__ float g_u32[(size_t)H_ * G4_];       // 4 MB: tf32-rounded recurrent kernel
__device__ float g_hT[(size_t)H_ * B_];         // 2 MB: tf32-rounded h, TRANSPOSED [H][B]
__device__ float g_c[(size_t)B_ * H_];          // 2 MB: cell state

// ---------------- helpers ---------------------------------------------------
__device__ __forceinline__ uint32_t f2tf32(float f) {
    uint32_t r;
    asm("cvt.rna.tf32.f32 %0, %1;" : "=r"(r) : "f"(f));
    return r;
}
__device__ __forceinline__ float rtf(float f) { return __uint_as_float(f2tf32(f)); }

__device__ __forceinline__ void mma8(float* c, const uint32_t* a, const uint32_t* b) {
    asm volatile(
        "mma.sync.aligned.m16n8k8.row.col.f32.tf32.tf32.f32 "
        "{%0,%1,%2,%3}, {%4,%5,%6,%7}, {%8,%9}, {%0,%1,%2,%3};\n"
        : "+f"(c[0]), "+f"(c[1]), "+f"(c[2]), "+f"(c[3])
        : "r"(a[0]), "r"(a[1]), "r"(a[2]), "r"(a[3]),
          "r"(b[0]), "r"(b[1]));
}

__device__ __forceinline__ float sigm(float x) { return 1.0f / (1.0f + __expf(-x)); }
// overflow-safe tanh: 1 - 2/(e^{2x}+1)  (inf -> 1, 0 -> -1; no inf/inf NaN)
__device__ __forceinline__ float tanh_(float x) { return 1.0f - 2.0f / (__expf(2.0f * x) + 1.0f); }

__device__ __forceinline__ void cp16(uint32_t s, const void* g) {
    asm volatile("cp.async.cg.shared.global [%0], [%1], 16;\n" :: "r"(s), "l"(g));
}
__device__ __forceinline__ void cpcommit() { asm volatile("cp.async.commit_group;\n"); }
template<int N> __device__ __forceinline__ void cpwait() {
    asm volatile("cp.async.wait_group %0;\n" :: "n"(N));
}

// ---------------- prep kernels ----------------------------------------------
__global__ void round_wu(const float* __restrict__ W, const float* __restrict__ U) {
    const int i = blockIdx.x * blockDim.x + threadIdx.x;   // D_*G4_ = 1M elems each
    g_w32[i] = rtf(W[i]);
    g_u32[i] = rtf(U[i]);
}

// X[b][t][k] -> g_xt[t][k][b], rounded to tf32
__global__ void prep_xt(const float* __restrict__ X) {
    __shared__ float tile[32][33];
    const int t = blockIdx.z, k0 = blockIdx.x * 32, b0 = blockIdx.y * 32;
    const int tx = threadIdx.x, ty = threadIdx.y;
#pragma unroll
    for (int i = 0; i < 4; i++)
        tile[ty + i * 8][tx] = X[((size_t)(b0 + ty + i * 8) * T_ + t) * D_ + k0 + tx];
    __syncthreads();
#pragma unroll
    for (int i = 0; i < 4; i++)
        g_xt[((size_t)t * D_ + k0 + ty + i * 8) * B_ + b0 + tx] = rtf(tile[tx][ty + i * 8]);
}

__global__ void zero_hc() {
    const int i = blockIdx.x * blockDim.x + threadIdx.x;   // B_*H_ = 524288
    g_hT[i] = 0.0f;
    g_c[i]  = 0.0f;
}

// ---------------- pipelined tf32 GEMM ---------------------------------------
// MODE 0: XP = Xperm @ W + bias       grid (G4_/128, T_*B_/128) = (16, 512)
// MODE 1: z  = h @ U + XP[t]; fused LSTM cell epilogue
//         grid (H_/32, B_/128) = (16, 8); CTA covers 128 rows x (32 hid x 4 gates)
constexpr int AROW = 136;                       // 128 + 8 pad: conflict-free frag LDS
constexpr int BROW = 128;
constexpr int STW  = 16 * AROW + 16 * BROW;     // words per stage = 4224
constexpr int SMEM_BYTES = 3 * STW * 4;         // 50688

template<int MODE>
__global__ void __launch_bounds__(256, 1)
gemm_k(const float* __restrict__ bias, float* __restrict__ out, int t)
{
    extern __shared__ __align__(16) uint32_t sm[];
    const uint32_t sbase = (uint32_t)__cvta_generic_to_shared(sm);

    const int tid = threadIdx.x;
    const int bx = blockIdx.x, by = blockIdx.y;

    // A base: rows are K, cols are batch (both sources are [.., K, B] layout)
    const float* Abase;
    int m0;
    if (MODE == 0) { const int tt = by >> 3; m0 = (by & 7) * 128; Abase = g_xt + (size_t)tt * D_ * B_; }
    else           { m0 = by * 128; Abase = g_hT; }

    // ---- cp.async loader mapping: 2 x 16B chunks per thread for A and B
    int offA[2], offB[2];
    const float* aG[2];
    const float* bG[2];
#pragma unroll
    for (int c = 0; c < 2; c++) {
        const int ch = tid + c * 256;
        const int k = ch >> 5, m4 = (ch & 31) * 4;
        offA[c] = k * AROW + m4;
        aG[c]   = Abase + (size_t)k * B_ + m0 + m4;
        offB[c] = 16 * AROW + k * BROW + m4;
        int col;
        if (MODE == 0) col = bx * 128 + m4;
        else { const int gate = m4 >> 5, hid = m4 & 31; col = gate * H_ + bx * 32 + hid; }
        const float* Bbase = (MODE == 0) ? g_w32 : g_u32;
        bG[c] = Bbase + (size_t)k * G4_ + col;
    }

    const int warp = tid >> 5, lane = tid & 31;
    const int wm = warp >> 2, wn = warp & 3;
    const int gq = lane >> 2, tq = lane & 3;

    float acc[4][4][4] = {};

    auto ISSUE = [&](int kt, int s) {
#pragma unroll
        for (int c = 0; c < 2; c++) {
            cp16(sbase + (uint32_t)(s * STW + offA[c]) * 4u, aG[c] + (size_t)kt * 16 * B_);
            cp16(sbase + (uint32_t)(s * STW + offB[c]) * 4u, bG[c] + (size_t)kt * 16 * G4_);
        }
    };

    ISSUE(0, 0); cpcommit();
    ISSUE(1, 1); cpcommit();

    for (int kt = 0; kt < D_ / 16; kt++) {
        cpwait<1>();
        __syncthreads();
        if (kt + 2 < D_ / 16) ISSUE(kt + 2, (kt + 2) % 3);
        cpcommit();

        const uint32_t* As  = sm + (kt % 3) * STW;
        const uint32_t* Bsm = As + 16 * AROW;
#pragma unroll
        for (int k8 = 0; k8 < 16; k8 += 8) {
            uint32_t afr[4][4], bfr[4][2];
#pragma unroll
            for (int mf = 0; mf < 4; mf++) {
                const int r0 = wm * 64 + mf * 16 + gq;
                afr[mf][0] = As[(k8 + tq) * AROW + r0];
                afr[mf][1] = As[(k8 + tq) * AROW + r0 + 8];
                afr[mf][2] = As[(k8 + tq + 4) * AROW + r0];
                afr[mf][3] = As[(k8 + tq + 4) * AROW + r0 + 8];
            }
#pragma unroll
            for (int nf = 0; nf < 4; nf++) {
                const int c0 = (MODE == 0) ? (wn * 32 + nf * 8 + gq) : (nf * 32 + wn * 8 + gq);
                bfr[nf][0] = Bsm[(k8 + tq) * BROW + c0];
                bfr[nf][1] = Bsm[(k8 + tq + 4) * BROW + c0];
            }
#pragma unroll
            for (int mf = 0; mf < 4; mf++)
#pragma unroll
                for (int nf = 0; nf < 4; nf++)
                    mma8(acc[mf][nf], afr[mf], bfr[nf]);
        }
    }

    // ---- epilogue
    if (MODE == 0) {
        const int n0 = bx * 128;
#pragma unroll
        for (int mf = 0; mf < 4; mf++)
#pragma unroll
            for (int nf = 0; nf < 4; nf++) {
                const int row = by * 128 + wm * 64 + mf * 16 + gq;
                const int col = n0 + wn * 32 + nf * 8 + tq * 2;
                const float b0v = bias[col], b1v = bias[col + 1];
                float2 v0 = make_float2(acc[mf][nf][0] + b0v, acc[mf][nf][1] + b1v);
                float2 v1 = make_float2(acc[mf][nf][2] + b0v, acc[mf][nf][3] + b1v);
                *(float2*)&g_xp[(size_t)row * G4_ + col] = v0;
                *(float2*)&g_xp[(size_t)(row + 8) * G4_ + col] = v1;
            }
    } else {
        // thread's 4 N-fragments = the 4 gates (i,f,g,o) for 2 hidden units
        const int hid0 = bx * 32 + wn * 8 + tq * 2;
#pragma unroll
        for (int mf = 0; mf < 4; mf++) {
#pragma unroll
            for (int rh = 0; rh < 2; rh++) {
                const int r = by * 128 + wm * 64 + mf * 16 + rh * 8 + gq;
                const float* xp = g_xp + ((size_t)t * B_ + r) * G4_;
                float z[4][2];
#pragma unroll
                for (int g = 0; g < 4; g++) {
                    const float2 x2 = *(const float2*)&xp[g * H_ + hid0];
                    z[g][0] = acc[mf][g][rh * 2 + 0] + x2.x;
                    z[g][1] = acc[mf][g][rh * 2 + 1] + x2.y;
                }
                float2 cc = *(float2*)&g_c[(size_t)r * H_ + hid0];
                float2 hh;
                {
                    const float ii = sigm(z[0][0]), ff = sigm(z[1][0]);
                    const float gg = tanh_(z[2][0]), oo = sigm(z[3][0]);
                    cc.x = ff * cc.x + ii * gg;
                    hh.x = oo * tanh_(cc.x);
                }
                {
                    const float ii = sigm(z[0][1]), ff = sigm(z[1][1]);
                    const float gg = tanh_(z[2][1]), oo = sigm(z[3][1]);
                    cc.y = ff * cc.y + ii * gg;
                    hh.y = oo * tanh_(cc.y);
                }
                *(float2*)&g_c[(size_t)r * H_ + hid0] = cc;
                *(float2*)&out[((size_t)r * T_ + t) * H_ + hid0] = hh;
                // transposed, tf32-rounded copy for the next step's A operand
                g_hT[(size_t)hid0 * B_ + r]       = rtf(hh.x);
                g_hT[(size_t)(hid0 + 1) * B_ + r] = rtf(hh.y);
            }
        }
    }
}

// ---------------- launch -----------------------------------------------------
extern "C" void kernel_launch(void* const* d_in, const int* in_sizes, int n_in,
                              void* d_out, int out_size)
{
    const float* X    = (const float*)d_in[0];   // [B, T, D]
    const float* W    = (const float*)d_in[1];   // [D, 4H]
    const float* U    = (const float*)d_in[2];   // [H, 4H]
    const float* bias = (const float*)d_in[3];   // [4H]
    float* out = (float*)d_out;                  // [B, T, H]

    cudaFuncSetAttribute(gemm_k<0>, cudaFuncAttributeMaxDynamicSharedMemorySize, SMEM_BYTES);
    cudaFuncSetAttribute(gemm_k<1>, cudaFuncAttributeMaxDynamicSharedMemorySize, SMEM_BYTES);

    round_wu<<<(D_ * G4_) / 256, 256>>>(W, U);
    prep_xt<<<dim3(D_ / 32, B_ / 32, T_), dim3(32, 8)>>>(X);
    zero_hc<<<(B_ * H_) / 256, 256>>>();

    // Stage 1: big parallel input projection
    gemm_k<0><<<dim3(G4_ / 128, (T_ * B_) / 128), 256, SMEM_BYTES>>>(bias, out, 0);

    // Stage 2: 64 fused recurrent steps (GEMM + LSTM cell in one kernel)
    for (int t = 0; t < T_; t++)
        gemm_k<1><<<dim3(H_ / 32, B_ / 128), 256, SMEM_BYTES>>>(bias, out, t);
}

// round 5
// speedup vs baseline: 1.6163x; 1.4339x over previous
#include <cuda_runtime.h>
#include <cstdint>

#define B_   1024
#define T_   64
#define D_   512
#define H_   512
#define G4_  2048   // 4*H

// ---------------- device scratch (no allocation allowed) --------------------
__device__ float g_xp[(size_t)T_ * B_ * G4_];   // 512 MB: x@W + bias, [T][B][4H]
__device__ float g_xt[(size_t)T_ * D_ * B_];    // 128 MB: tf32-rounded X, [T][D][B]
__device__ float g_w32[(size_t)D_ * G4_];       // 4 MB: tf32-rounded kernel [D][4H]
__device__ float g_u32[(size_t)H_ * G4_];       // 4 MB: tf32-rounded recurrent kernel
__device__ float g_hT[2][(size_t)H_ * B_];      // 2x2 MB: rounded h, TRANSPOSED [H][B], ping-pong
__device__ float g_c[(size_t)B_ * H_];          // 2 MB: cell state

// ---------------- helpers ---------------------------------------------------
__device__ __forceinline__ uint32_t f2tf32(float f) {
    uint32_t r;
    asm("cvt.rna.tf32.f32 %0, %1;" : "=r"(r) : "f"(f));
    return r;
}
__device__ __forceinline__ float rtf(float f) { return __uint_as_float(f2tf32(f)); }

__device__ __forceinline__ void mma8(float* c, const uint32_t* a, const uint32_t* b) {
    asm volatile(
        "mma.sync.aligned.m16n8k8.row.col.f32.tf32.tf32.f32 "
        "{%0,%1,%2,%3}, {%4,%5,%6,%7}, {%8,%9}, {%0,%1,%2,%3};\n"
        : "+f"(c[0]), "+f"(c[1]), "+f"(c[2]), "+f"(c[3])
        : "r"(a[0]), "r"(a[1]), "r"(a[2]), "r"(a[3]),
          "r"(b[0]), "r"(b[1]));
}

__device__ __forceinline__ float sigm(float x) { return 1.0f / (1.0f + __expf(-x)); }
// overflow-safe tanh: 1 - 2/(e^{2x}+1)
__device__ __forceinline__ float tanh_(float x) { return 1.0f - 2.0f / (__expf(2.0f * x) + 1.0f); }

__device__ __forceinline__ void cp16(uint32_t s, const void* g) {
    asm volatile("cp.async.cg.shared.global [%0], [%1], 16;\n" :: "r"(s), "l"(g));
}
__device__ __forceinline__ void cpcommit() { asm volatile("cp.async.commit_group;\n"); }
template<int N> __device__ __forceinline__ void cpwait() {
    asm volatile("cp.async.wait_group %0;\n" :: "n"(N));
}

// ---------------- prep kernels ----------------------------------------------
__global__ void round_wu(const float* __restrict__ W, const float* __restrict__ U) {
    const int i = blockIdx.x * blockDim.x + threadIdx.x;   // D_*G4_ = 1M each
    g_w32[i] = rtf(W[i]);
    g_u32[i] = rtf(U[i]);
}

// X[b][t][k] -> g_xt[t][k][b], rounded to tf32
__global__ void prep_xt(const float* __restrict__ X) {
    __shared__ float tile[32][33];
    const int t = blockIdx.z, k0 = blockIdx.x * 32, b0 = blockIdx.y * 32;
    const int tx = threadIdx.x, ty = threadIdx.y;
#pragma unroll
    for (int i = 0; i < 4; i++)
        tile[ty + i * 8][tx] = X[((size_t)(b0 + ty + i * 8) * T_ + t) * D_ + k0 + tx];
    __syncthreads();
#pragma unroll
    for (int i = 0; i < 4; i++)
        g_xt[((size_t)t * D_ + k0 + ty + i * 8) * B_ + b0 + tx] = rtf(tile[tx][ty + i * 8]);
}

__global__ void zero_hc() {
    const int i = blockIdx.x * blockDim.x + threadIdx.x;   // B_*H_
    g_hT[0][i] = 0.0f;
    g_hT[1][i] = 0.0f;
    g_c[i]     = 0.0f;
}

// ---------------- pipelined tf32 GEMM ---------------------------------------
// MODE 0: XP = Xperm @ W + bias   tiles 128x128, grid (16, 512)
// MODE 1: z  = h @ U + XP[t]; fused LSTM cell epilogue
//         tiles 64x128, grid (16, 16); N cols gate-major (nf -> gate)
//         h is ping-pong buffered: read g_hT[t&1], write g_hT[(t+1)&1]  (race-free)
template<int MODE>
__global__ void __launch_bounds__(256, 2)
gemm_k(const float* __restrict__ bias, float* __restrict__ out, int t)
{
    constexpr int BM   = (MODE == 0) ? 128 : 64;
    constexpr int MF   = BM / 32;                  // M fragments per warp (4 / 2)
    constexpr int AROW = BM + 8;                   // 136 / 72  (mod 32 == 8)
    constexpr int BROW = 136;                      // 128 + 8: conflict-free B LDS
    constexpr int STW  = 16 * AROW + 16 * BROW;    // words per stage
    constexpr int NA   = BM / 64;                  // A 16B-chunks per thread (2/1)
    constexpr int AC   = BM / 4;                   // A chunks per k-row

    extern __shared__ __align__(16) uint32_t sm[];
    const uint32_t sbase = (uint32_t)__cvta_generic_to_shared(sm);

    const int tid = threadIdx.x;
    const int bx = blockIdx.x, by = blockIdx.y;

    // A base: rows are K, cols are batch ([.., K, B] layouts)
    const float* Abase;
    if (MODE == 0) { const int tt = by >> 3; Abase = g_xt + (size_t)tt * D_ * B_ + (by & 7) * 128; }
    else           { Abase = g_hT[t & 1] + by * 64; }

    // ---- cp.async loader mapping
    uint32_t offA[NA];
    const float* aG[NA];
#pragma unroll
    for (int c = 0; c < NA; c++) {
        const int q = tid + c * 256;
        const int k = q / AC, m4 = (q % AC) * 4;
        offA[c] = (uint32_t)(k * AROW + m4);
        aG[c]   = Abase + (size_t)k * B_ + m4;
    }
    uint32_t offB[2];
    const float* bG[2];
#pragma unroll
    for (int c = 0; c < 2; c++) {
        const int q = tid + c * 256;
        const int k = q >> 5, m4 = (q & 31) * 4;
        offB[c] = (uint32_t)(16 * AROW + k * BROW + m4);
        int col;
        if (MODE == 0) col = bx * 128 + m4;
        else { const int gate = m4 >> 5, hid = m4 & 31; col = gate * H_ + bx * 32 + hid; }
        const float* Bbase = (MODE == 0) ? g_w32 : g_u32;
        bG[c] = Bbase + (size_t)k * G4_ + col;
    }

    const int warp = tid >> 5, lane = tid & 31;
    const int wm = warp >> 2, wn = warp & 3;
    const int gq = lane >> 2, tq = lane & 3;

    float acc[MF][4][4] = {};

    auto ISSUE = [&](int kt, int s) {
#pragma unroll
        for (int c = 0; c < NA; c++)
            cp16(sbase + (uint32_t)(s * STW + offA[c]) * 4u, aG[c] + (size_t)kt * 16 * B_);
#pragma unroll
        for (int c = 0; c < 2; c++)
            cp16(sbase + (uint32_t)(s * STW + offB[c]) * 4u, bG[c] + (size_t)kt * 16 * G4_);
    };

    ISSUE(0, 0); cpcommit();
    ISSUE(1, 1); cpcommit();

    for (int kt = 0; kt < D_ / 16; kt++) {
        cpwait<1>();
        __syncthreads();
        if (kt + 2 < D_ / 16) ISSUE(kt + 2, (kt + 2) % 3);
        cpcommit();

        const uint32_t* As  = sm + (kt % 3) * STW;
        const uint32_t* Bsm = As + 16 * AROW;
#pragma unroll
        for (int k8 = 0; k8 < 16; k8 += 8) {
            uint32_t afr[MF][4], bfr[4][2];
#pragma unroll
            for (int mf = 0; mf < MF; mf++) {
                const int r0 = wm * (MF * 16) + mf * 16 + gq;
                afr[mf][0] = As[(k8 + tq) * AROW + r0];
                afr[mf][1] = As[(k8 + tq) * AROW + r0 + 8];
                afr[mf][2] = As[(k8 + tq + 4) * AROW + r0];
                afr[mf][3] = As[(k8 + tq + 4) * AROW + r0 + 8];
            }
#pragma unroll
            for (int nf = 0; nf < 4; nf++) {
                const int c0 = (MODE == 0) ? (wn * 32 + nf * 8 + gq) : (nf * 32 + wn * 8 + gq);
                bfr[nf][0] = Bsm[(k8 + tq) * BROW + c0];
                bfr[nf][1] = Bsm[(k8 + tq + 4) * BROW + c0];
            }
#pragma unroll
            for (int mf = 0; mf < MF; mf++)
#pragma unroll
                for (int nf = 0; nf < 4; nf++)
                    mma8(acc[mf][nf], afr[mf], bfr[nf]);
        }
    }
    __syncthreads();

    // ---- epilogue
    if (MODE == 0) {
        const int n0 = bx * 128;
#pragma unroll
        for (int mf = 0; mf < MF; mf++)
#pragma unroll
            for (int nf = 0; nf < 4; nf++) {
                const int row = by * 128 + wm * 64 + mf * 16 + gq;   // = t*B_ + b
                const int col = n0 + wn * 32 + nf * 8 + tq * 2;
                const float b0v = bias[col], b1v = bias[col + 1];
                float2 v0 = make_float2(acc[mf][nf][0] + b0v, acc[mf][nf][1] + b1v);
                float2 v1 = make_float2(acc[mf][nf][2] + b0v, acc[mf][nf][3] + b1v);
                *(float2*)&g_xp[(size_t)row * G4_ + col] = v0;
                *(float2*)&g_xp[(size_t)(row + 8) * G4_ + col] = v1;
            }
    } else {
        // thread's 4 N-fragments are the 4 gates (i,f,g,o) for 2 hidden units
        float* hW = g_hT[(t + 1) & 1];
        const int hid0 = bx * 32 + wn * 8 + tq * 2;
#pragma unroll
        for (int mf = 0; mf < MF; mf++) {
#pragma unroll
            for (int rh = 0; rh < 2; rh++) {
                const int r = by * 64 + wm * 32 + mf * 16 + rh * 8 + gq;   // batch
                const float* xp = g_xp + ((size_t)t * B_ + r) * G4_;
                float z[4][2];
#pragma unroll
                for (int g = 0; g < 4; g++) {
                    const float2 x2 = *(const float2*)&xp[g * H_ + hid0];
                    z[g][0] = acc[mf][g][rh * 2 + 0] + x2.x;
                    z[g][1] = acc[mf][g][rh * 2 + 1] + x2.y;
                }
                float2 cc = *(float2*)&g_c[(size_t)r * H_ + hid0];
                float2 hh;
                {
                    const float ii = sigm(z[0][0]), ff = sigm(z[1][0]);
                    const float gg = tanh_(z[2][0]), oo = sigm(z[3][0]);
                    cc.x = ff * cc.x + ii * gg;
                    hh.x = oo * tanh_(cc.x);
                }
                {
                    const float ii = sigm(z[0][1]), ff = sigm(z[1][1]);
                    const float gg = tanh_(z[2][1]), oo = sigm(z[3][1]);
                    cc.y = ff * cc.y + ii * gg;
                    hh.y = oo * tanh_(cc.y);
                }
                *(float2*)&g_c[(size_t)r * H_ + hid0] = cc;
                *(float2*)&out[((size_t)r * T_ + t) * H_ + hid0] = hh;
                hW[(size_t)hid0 * B_ + r]       = rtf(hh.x);
                hW[(size_t)(hid0 + 1) * B_ + r] = rtf(hh.y);
            }
        }
    }
}

// ---------------- launch -----------------------------------------------------
extern "C" void kernel_launch(void* const* d_in, const int* in_sizes, int n_in,
                              void* d_out, int out_size)
{
    const float* X    = (const float*)d_in[0];   // [B, T, D]
    const float* W    = (const float*)d_in[1];   // [D, 4H]
    const float* U    = (const float*)d_in[2];   // [H, 4H]
    const float* bias = (const float*)d_in[3];   // [4H]
    float* out = (float*)d_out;                  // [B, T, H]

    constexpr int SM0 = 3 * (16 * 136 + 16 * 136) * 4;   // 52224 B
    constexpr int SM1 = 3 * (16 * 72  + 16 * 136) * 4;   // 39936 B
    cudaFuncSetAttribute(gemm_k<0>, cudaFuncAttributeMaxDynamicSharedMemorySize, SM0);
    cudaFuncSetAttribute(gemm_k<1>, cudaFuncAttributeMaxDynamicSharedMemorySize, SM1);

    round_wu<<<(D_ * G4_) / 256, 256>>>(W, U);
    prep_xt<<<dim3(D_ / 32, B_ / 32, T_), dim3(32, 8)>>>(X);
    zero_hc<<<(B_ * H_) / 256, 256>>>();

    // Stage 1: big parallel input projection (128x128 tiles)
    gemm_k<0><<<dim3(G4_ / 128, (T_ * B_) / 128), 256, SM0>>>(bias, out, 0);

    // Stage 2: 64 fused recurrent steps (64x128 tiles -> 256 CTAs/step)
    for (int t = 0; t < T_; t++)
        gemm_k<1><<<dim3(H_ / 32, B_ / 64), 256, SM1>>>(bias, out, t);
}

// round 6
// speedup vs baseline: 1.7826x; 1.1029x over previous
#include <cuda_runtime.h>
#include <cstdint>

#define B_   1024
#define T_   64
#define D_   512
#define H_   512
#define G4_  2048   // 4*H

// ---------------- device scratch (no allocation allowed) --------------------
__device__ float g_xp[(size_t)T_ * B_ * G4_];   // 512 MB: x@W + bias, [T][B][4H]
__device__ float g_xt[(size_t)T_ * D_ * B_];    // 128 MB: tf32-rounded X, [T][D][B]
__device__ float g_w32[(size_t)D_ * G4_];       // 4 MB: tf32-rounded kernel [D][4H]
__device__ float g_u32[(size_t)H_ * G4_];       // 4 MB: tf32-rounded recurrent kernel
__device__ float g_hT[2][(size_t)H_ * B_];      // 2x2 MB: rounded h, TRANSPOSED [H][B], ping-pong
__device__ unsigned g_bar[16];                  // per-by-group step barrier counters

// ---------------- helpers ---------------------------------------------------
__device__ __forceinline__ uint32_t f2tf32(float f) {
    uint32_t r;
    asm("cvt.rna.tf32.f32 %0, %1;" : "=r"(r) : "f"(f));
    return r;
}
__device__ __forceinline__ float rtf(float f) { return __uint_as_float(f2tf32(f)); }

__device__ __forceinline__ void mma8(float* c, const uint32_t* a, const uint32_t* b) {
    asm volatile(
        "mma.sync.aligned.m16n8k8.row.col.f32.tf32.tf32.f32 "
        "{%0,%1,%2,%3}, {%4,%5,%6,%7}, {%8,%9}, {%0,%1,%2,%3};\n"
        : "+f"(c[0]), "+f"(c[1]), "+f"(c[2]), "+f"(c[3])
        : "r"(a[0]), "r"(a[1]), "r"(a[2]), "r"(a[3]),
          "r"(b[0]), "r"(b[1]));
}

__device__ __forceinline__ float sigm(float x) { return 1.0f / (1.0f + __expf(-x)); }
__device__ __forceinline__ float tanh_(float x) { return 1.0f - 2.0f / (__expf(2.0f * x) + 1.0f); }

__device__ __forceinline__ void cp16(uint32_t s, const void* g) {
    asm volatile("cp.async.cg.shared.global [%0], [%1], 16;\n" :: "r"(s), "l"(g));
}
__device__ __forceinline__ void cpcommit() { asm volatile("cp.async.commit_group;\n"); }
template<int N> __device__ __forceinline__ void cpwait() {
    asm volatile("cp.async.wait_group %0;\n" :: "n"(N));
}

// ---------------- prep kernels ----------------------------------------------
__global__ void round_wu(const float* __restrict__ W, const float* __restrict__ U) {
    const int i = blockIdx.x * blockDim.x + threadIdx.x;   // D_*G4_ = 1M each
    g_w32[i] = rtf(W[i]);
    g_u32[i] = rtf(U[i]);
}

// X[b][t][k] -> g_xt[t][k][b], rounded to tf32
__global__ void prep_xt(const float* __restrict__ X) {
    __shared__ float tile[32][33];
    const int t = blockIdx.z, k0 = blockIdx.x * 32, b0 = blockIdx.y * 32;
    const int tx = threadIdx.x, ty = threadIdx.y;
#pragma unroll
    for (int i = 0; i < 4; i++)
        tile[ty + i * 8][tx] = X[((size_t)(b0 + ty + i * 8) * T_ + t) * D_ + k0 + tx];
    __syncthreads();
#pragma unroll
    for (int i = 0; i < 4; i++)
        g_xt[((size_t)t * D_ + k0 + ty + i * 8) * B_ + b0 + tx] = rtf(tile[tx][ty + i * 8]);
}

__global__ void zero_state() {
    const int i = blockIdx.x * blockDim.x + threadIdx.x;   // B_*H_
    g_hT[0][i] = 0.0f;
    g_hT[1][i] = 0.0f;
    if (i < 16) g_bar[i] = 0u;
}

// ---------------- stage 1: pipelined tf32 GEMM (unchanged from R5) ----------
// XP = Xperm @ W + bias, tiles 128x128, grid (16, 512)
__global__ void __launch_bounds__(256, 2)
gemm_x(const float* __restrict__ bias)
{
    constexpr int AROW = 136, BROW = 136;
    constexpr int STW  = 16 * AROW + 16 * BROW;

    extern __shared__ __align__(16) uint32_t sm[];
    const uint32_t sbase = (uint32_t)__cvta_generic_to_shared(sm);

    const int tid = threadIdx.x;
    const int bx = blockIdx.x, by = blockIdx.y;

    const int tt = by >> 3;
    const float* Abase = g_xt + (size_t)tt * D_ * B_ + (by & 7) * 128;

    uint32_t offA[2];
    const float* aG[2];
#pragma unroll
    for (int c = 0; c < 2; c++) {
        const int q = tid + c * 256;
        const int k = q >> 5, m4 = (q & 31) * 4;
        offA[c] = (uint32_t)(k * AROW + m4);
        aG[c]   = Abase + (size_t)k * B_ + m4;
    }
    uint32_t offB[2];
    const float* bG[2];
#pragma unroll
    for (int c = 0; c < 2; c++) {
        const int q = tid + c * 256;
        const int k = q >> 5, m4 = (q & 31) * 4;
        offB[c] = (uint32_t)(16 * AROW + k * BROW + m4);
        bG[c] = g_w32 + (size_t)k * G4_ + bx * 128 + m4;
    }

    const int warp = tid >> 5, lane = tid & 31;
    const int wm = warp >> 2, wn = warp & 3;
    const int gq = lane >> 2, tq = lane & 3;

    float acc[4][4][4] = {};

    auto ISSUE = [&](int kt, int s) {
#pragma unroll
        for (int c = 0; c < 2; c++)
            cp16(sbase + (uint32_t)(s * STW + offA[c]) * 4u, aG[c] + (size_t)kt * 16 * B_);
#pragma unroll
        for (int c = 0; c < 2; c++)
            cp16(sbase + (uint32_t)(s * STW + offB[c]) * 4u, bG[c] + (size_t)kt * 16 * G4_);
    };

    ISSUE(0, 0); cpcommit();
    ISSUE(1, 1); cpcommit();

    for (int kt = 0; kt < D_ / 16; kt++) {
        cpwait<1>();
        __syncthreads();
        if (kt + 2 < D_ / 16) ISSUE(kt + 2, (kt + 2) % 3);
        cpcommit();

        const uint32_t* As  = sm + (kt % 3) * STW;
        const uint32_t* Bsm = As + 16 * AROW;
#pragma unroll
        for (int k8 = 0; k8 < 16; k8 += 8) {
            uint32_t afr[4][4], bfr[4][2];
#pragma unroll
            for (int mf = 0; mf < 4; mf++) {
                const int r0 = wm * 64 + mf * 16 + gq;
                afr[mf][0] = As[(k8 + tq) * AROW + r0];
                afr[mf][1] = As[(k8 + tq) * AROW + r0 + 8];
                afr[mf][2] = As[(k8 + tq + 4) * AROW + r0];
                afr[mf][3] = As[(k8 + tq + 4) * AROW + r0 + 8];
            }
#pragma unroll
            for (int nf = 0; nf < 4; nf++) {
                const int c0 = wn * 32 + nf * 8 + gq;
                bfr[nf][0] = Bsm[(k8 + tq) * BROW + c0];
                bfr[nf][1] = Bsm[(k8 + tq + 4) * BROW + c0];
            }
#pragma unroll
            for (int mf = 0; mf < 4; mf++)
#pragma unroll
                for (int nf = 0; nf < 4; nf++)
                    mma8(acc[mf][nf], afr[mf], bfr[nf]);
        }
    }
    __syncthreads();

    const int n0 = bx * 128;
#pragma unroll
    for (int mf = 0; mf < 4; mf++)
#pragma unroll
        for (int nf = 0; nf < 4; nf++) {
            const int row = by * 128 + wm * 64 + mf * 16 + gq;   // = t*B_ + b
            const int col = n0 + wn * 32 + nf * 8 + tq * 2;
            const float b0v = bias[col], b1v = bias[col + 1];
            float2 v0 = make_float2(acc[mf][nf][0] + b0v, acc[mf][nf][1] + b1v);
            float2 v1 = make_float2(acc[mf][nf][2] + b0v, acc[mf][nf][3] + b1v);
            *(float2*)&g_xp[(size_t)row * G4_ + col] = v0;
            *(float2*)&g_xp[(size_t)(row + 8) * G4_ + col] = v1;
        }
}

// ---------------- stage 2: persistent recurrent kernel ----------------------
// grid (16, 16): bx = 32-hid slice, by = 64-batch slice. All 64 steps inside.
// Per-by-group spin barrier between steps; c lives in registers; xp tile
// prefetched into smem during the mainloop.
__global__ void __launch_bounds__(256, 2)
lstm_rec(float* __restrict__ out)
{
    constexpr int AROW = 72, BROW = 136;
    constexpr int STW  = 16 * AROW + 16 * BROW;   // 3328 words
    constexpr int XPW  = 3 * STW;                 // xp smem offset (words) = 9984
    constexpr int XROW = 132;                     // xp row stride (pad: kills LDS conflicts)

    extern __shared__ __align__(16) uint32_t sm[];
    const uint32_t sbase = (uint32_t)__cvta_generic_to_shared(sm);
    const float* xp_sm = (const float*)sm + XPW;

    const int tid = threadIdx.x;
    const int bx = blockIdx.x, by = blockIdx.y;

    // ---- A (h) loader: 1 chunk per thread
    const int ka  = tid >> 4;               // 0..15
    const int am4 = (tid & 15) * 4;         // 0..60
    const uint32_t offA = (uint32_t)(ka * AROW + am4);
    const size_t   aoff = (size_t)ka * B_ + by * 64 + am4;

    // ---- B (U) loader: 2 chunks per thread (gate-major cols)
    uint32_t offB[2];
    const float* bG[2];
#pragma unroll
    for (int c = 0; c < 2; c++) {
        const int q = tid + c * 256;
        const int k = q >> 5, m4 = (q & 31) * 4;
        offB[c] = (uint32_t)(16 * AROW + k * BROW + m4);
        const int gate = m4 >> 5, hid = m4 & 31;
        bG[c] = g_u32 + (size_t)k * G4_ + gate * H_ + bx * 32 + hid;
    }

    // ---- xp loader: 8 groups x 16B per thread covers 64x128 tile
    const int xr = tid >> 5;                // row 0..7 (plus 8*g)
    const int xc = (tid & 31) * 4;          // col 0..124
    const size_t xsrc0 = ((size_t)(by * 64 + xr)) * G4_
                       + (xc >> 5) * H_ + bx * 32 + (xc & 31);

    const int warp = tid >> 5, lane = tid & 31;
    const int wm = warp >> 2, wn = warp & 3;
    const int gq = lane >> 2, tq = lane & 3;
    const int hidl = wn * 8 + tq * 2;

    float cst[2][2][2] = {};                // cell state, registers only

    for (int t = 0; t < T_; t++) {
        const float* hbase = g_hT[t & 1];
        float*       hW    = g_hT[(t + 1) & 1];
        const size_t xstep = (size_t)t * B_ * G4_;

        float acc[2][4][4] = {};

        auto ISSUE = [&](int kt) {
            const uint32_t sb = sbase + (uint32_t)((kt % 3) * STW) * 4u;
            cp16(sb + offA * 4u, hbase + aoff + (size_t)kt * 16 * B_);
#pragma unroll
            for (int c = 0; c < 2; c++)
                cp16(sb + offB[c] * 4u, bG[c] + (size_t)kt * 16 * G4_);
            if (kt < 8)
                cp16(sbase + (uint32_t)(XPW + (xr + 8 * kt) * XROW + xc) * 4u,
                     g_xp + xstep + xsrc0 + (size_t)(8 * kt) * G4_);
        };

        ISSUE(0); cpcommit();
        ISSUE(1); cpcommit();

        for (int kt = 0; kt < H_ / 16; kt++) {
            cpwait<1>();
            __syncthreads();
            if (kt + 2 < H_ / 16) ISSUE(kt + 2);
            cpcommit();

            const uint32_t* As  = sm + (kt % 3) * STW;
            const uint32_t* Bsm = As + 16 * AROW;
#pragma unroll
            for (int k8 = 0; k8 < 16; k8 += 8) {
                uint32_t afr[2][4], bfr[4][2];
#pragma unroll
                for (int mf = 0; mf < 2; mf++) {
                    const int r0 = wm * 32 + mf * 16 + gq;
                    afr[mf][0] = As[(k8 + tq) * AROW + r0];
                    afr[mf][1] = As[(k8 + tq) * AROW + r0 + 8];
                    afr[mf][2] = As[(k8 + tq + 4) * AROW + r0];
                    afr[mf][3] = As[(k8 + tq + 4) * AROW + r0 + 8];
                }
#pragma unroll
                for (int nf = 0; nf < 4; nf++) {
                    const int c0 = nf * 32 + wn * 8 + gq;
                    bfr[nf][0] = Bsm[(k8 + tq) * BROW + c0];
                    bfr[nf][1] = Bsm[(k8 + tq + 4) * BROW + c0];
                }
#pragma unroll
                for (int mf = 0; mf < 2; mf++)
#pragma unroll
                    for (int nf = 0; nf < 4; nf++)
                        mma8(acc[mf][nf], afr[mf], bfr[nf]);
            }
        }

        // ---- fused LSTM cell epilogue (xp from smem, c in registers)
#pragma unroll
        for (int mf = 0; mf < 2; mf++) {
#pragma unroll
            for (int rh = 0; rh < 2; rh++) {
                const int rl = wm * 32 + mf * 16 + rh * 8 + gq;   // local batch row
                float z[4][2];
#pragma unroll
                for (int g = 0; g < 4; g++) {
                    z[g][0] = acc[mf][g][rh * 2 + 0] + xp_sm[rl * XROW + g * 32 + hidl];
                    z[g][1] = acc[mf][g][rh * 2 + 1] + xp_sm[rl * XROW + g * 32 + hidl + 1];
                }
                float2 hh;
                {
                    const float ii = sigm(z[0][0]), ff = sigm(z[1][0]);
                    const float gg = tanh_(z[2][0]), oo = sigm(z[3][0]);
                    cst[mf][rh][0] = ff * cst[mf][rh][0] + ii * gg;
                    hh.x = oo * tanh_(cst[mf][rh][0]);
                }
                {
                    const float ii = sigm(z[0][1]), ff = sigm(z[1][1]);
                    const float gg = tanh_(z[2][1]), oo = sigm(z[3][1]);
                    cst[mf][rh][1] = ff * cst[mf][rh][1] + ii * gg;
                    hh.y = oo * tanh_(cst[mf][rh][1]);
                }
                const int r = by * 64 + rl;
                *(float2*)&out[((size_t)r * T_ + t) * H_ + bx * 32 + hidl] = hh;
                hW[(size_t)(bx * 32 + hidl) * B_ + r]     = rtf(hh.x);
                hW[(size_t)(bx * 32 + hidl + 1) * B_ + r] = rtf(hh.y);
            }
        }

        // ---- per-by-group step barrier (16 CTAs)
        __syncthreads();
        if (tid == 0) {
            __threadfence();
            atomicAdd(&g_bar[by], 1u);
            const unsigned tgt = 16u * (unsigned)(t + 1);
            unsigned v;
            do {
                asm volatile("ld.acquire.gpu.u32 %0, [%1];"
                             : "=r"(v) : "l"(&g_bar[by]) : "memory");
                if (v < tgt) __nanosleep(20);
            } while (v < tgt);
        }
        __syncthreads();
    }
}

// ---------------- launch -----------------------------------------------------
extern "C" void kernel_launch(void* const* d_in, const int* in_sizes, int n_in,
                              void* d_out, int out_size)
{
    const float* X    = (const float*)d_in[0];   // [B, T, D]
    const float* W    = (const float*)d_in[1];   // [D, 4H]
    const float* U    = (const float*)d_in[2];   // [H, 4H]
    const float* bias = (const float*)d_in[3];   // [4H]
    float* out = (float*)d_out;                  // [B, T, H]

    constexpr int SM0 = 3 * (16 * 136 + 16 * 136) * 4;             // 52224 B
    constexpr int SM1 = (3 * (16 * 72 + 16 * 136) + 64 * 132) * 4; // 73728 B
    cudaFuncSetAttribute(gemm_x,   cudaFuncAttributeMaxDynamicSharedMemorySize, SM0);
    cudaFuncSetAttribute(lstm_rec, cudaFuncAttributeMaxDynamicSharedMemorySize, SM1);

    round_wu<<<(D_ * G4_) / 256, 256>>>(W, U);
    prep_xt<<<dim3(D_ / 32, B_ / 32, T_), dim3(32, 8)>>>(X);
    zero_state<<<(B_ * H_) / 256, 256>>>();

    // Stage 1: input projection (128x128 tiles)
    gemm_x<<<dim3(G4_ / 128, (T_ * B_) / 128), 256, SM0>>>(bias);

    // Stage 2: single persistent kernel runs all 64 recurrent steps
    lstm_rec<<<dim3(16, 16), 256, SM1>>>(out);
}